// round 13
// baseline (speedup 1.0000x reference)
#include <cuda_runtime.h>
#include <cuda_fp16.h>
#include <stdint.h>

// ---------------------------------------------------------------------------
// Winograd F(2,3) valid conv, fp16 mma.sync (m16n8k16, fp32 accum):
//   1) filt_xform : U[p][c][k] = G g G^T   (fp16)
//   2) in_xform   : V[p][c][t] = B^T d B   (fp16, 4 tiles/thread)
//   3) wino_gemm  : M[p][k][t] = sum_c U*V (fp16 HMMA, 32-c chunks, 4 iters)
//   4) out_xform  : Y = A^T M A + bias     (4 tiles/thread, uint2 M loads)
// t = (b*31+pp)*32 + qq (qq padded to 32), NTP = 31744.  Pad columns are
// never consumed (M[k][t] depends only on V[.][t]; out_xform skips pads).
// ---------------------------------------------------------------------------

#define Bn 32
#define Cc 128
#define Hh 64
#define Ww 64
#define Kk 256
#define NBR 992               /* tile rows: 32 b * 31 pp */
#define NTP 31744             /* 992 * 32 = 248 * 128 */
#define OH 62
#define OW 62

__device__ __half g_U16[16 * Cc * Kk];    //   1 MB  [p][c][k]
__device__ __half g_V16[16 * Cc * NTP];   // 130 MB  [p][c][t]
__device__ __half g_M16[16 * Kk * NTP];   // 260 MB  [p][k][t]

__device__ __forceinline__ uint32_t smem_u32(const void* p) {
    uint32_t a;
    asm("{ .reg .u64 t; cvta.to.shared.u64 t, %1; cvt.u32.u64 %0, t; }" : "=r"(a) : "l"(p));
    return a;
}
__device__ __forceinline__ void cp16(uint32_t dst, const void* src) {
    asm volatile("cp.async.cg.shared.global [%0], [%1], 16;" :: "r"(dst), "l"(src));
}
__device__ __forceinline__ void ldmx4(uint32_t* r, uint32_t addr) {
    asm volatile("ldmatrix.sync.aligned.m8n8.x4.trans.shared.b16 {%0,%1,%2,%3}, [%4];"
                 : "=r"(r[0]), "=r"(r[1]), "=r"(r[2]), "=r"(r[3]) : "r"(addr));
}
__device__ __forceinline__ void mma_f16(float* d, const uint32_t* a, const uint32_t* b) {
    asm volatile(
        "mma.sync.aligned.m16n8k16.row.col.f32.f16.f16.f32 "
        "{%0,%1,%2,%3}, {%4,%5,%6,%7}, {%8,%9}, {%0,%1,%2,%3};"
        : "+f"(d[0]), "+f"(d[1]), "+f"(d[2]), "+f"(d[3])
        : "r"(a[0]), "r"(a[1]), "r"(a[2]), "r"(a[3]), "r"(b[0]), "r"(b[1]));
}

// ---------------------------------------------------------------------------
// 1) Filter transform -> U[p][c][k] fp16
// ---------------------------------------------------------------------------
__global__ void filt_xform(const float* __restrict__ w)
{
    int idx = blockIdx.x * blockDim.x + threadIdx.x;   // 32768
    int k = idx >> 7;
    int c = idx & 127;
    const float* g = w + (size_t)(k * Cc + c) * 9;

    float w00 = g[0], w01 = g[1], w02 = g[2];
    float w10 = g[3], w11 = g[4], w12 = g[5];
    float w20 = g[6], w21 = g[7], w22 = g[8];

    float t[4][3];
    t[0][0] = w00;                      t[0][1] = w01;                      t[0][2] = w02;
    t[1][0] = 0.5f * (w00 + w10 + w20); t[1][1] = 0.5f * (w01 + w11 + w21); t[1][2] = 0.5f * (w02 + w12 + w22);
    t[2][0] = 0.5f * (w00 - w10 + w20); t[2][1] = 0.5f * (w01 - w11 + w21); t[2][2] = 0.5f * (w02 - w12 + w22);
    t[3][0] = w20;                      t[3][1] = w21;                      t[3][2] = w22;

    #pragma unroll
    for (int a = 0; a < 4; a++) {
        float u0 = t[a][0];
        float u1 = 0.5f * (t[a][0] + t[a][1] + t[a][2]);
        float u2 = 0.5f * (t[a][0] - t[a][1] + t[a][2]);
        float u3 = t[a][2];
        g_U16[((size_t)(a * 4 + 0) * Cc + c) * Kk + k] = __float2half_rn(u0);
        g_U16[((size_t)(a * 4 + 1) * Cc + c) * Kk + k] = __float2half_rn(u1);
        g_U16[((size_t)(a * 4 + 2) * Cc + c) * Kk + k] = __float2half_rn(u2);
        g_U16[((size_t)(a * 4 + 3) * Cc + c) * Kk + k] = __float2half_rn(u3);
    }
}

// ---------------------------------------------------------------------------
// 2) Input transform -> V[p][c][t], 4 horizontal tiles per thread.
//    Thread (c, brow, j): tiles qq = 4j..4j+3; j==7 -> tiles 28,29,30 (+pad).
//    Row transform (B^T d) over 10 shared columns computed once per a-row.
//    idx range = 128 * 992 * 8 = 1,015,808 = 3968 blocks * 256.
// ---------------------------------------------------------------------------
__global__ void __launch_bounds__(256) in_xform(const float* __restrict__ x)
{
    unsigned idx  = blockIdx.x * blockDim.x + threadIdx.x;
    unsigned j    = idx & 7u;
    unsigned rest = idx >> 3;           // c * 992 + brow
    unsigned c    = rest / NBR;
    unsigned brow = rest - c * NBR;
    unsigned b    = brow / 31u;
    unsigned pp   = brow - b * 31u;
    int qq0 = 4 * j;

    const float* xp = x + (((size_t)(b * Cc + c) * Hh + 2u * pp) * Ww + 2 * qq0);

    float d[4][10];
    if (j < 7) {
        #pragma unroll
        for (int i = 0; i < 4; i++) {
            #pragma unroll
            for (int s = 0; s < 5; s++) {
                float2 l = *(const float2*)(xp + i * Ww + 2 * s);
                d[i][2 * s] = l.x; d[i][2 * s + 1] = l.y;
            }
        }
    } else {                             // cols 56..63 only; 64,65 OOB -> 0
        #pragma unroll
        for (int i = 0; i < 4; i++) {
            #pragma unroll
            for (int s = 0; s < 4; s++) {
                float2 l = *(const float2*)(xp + i * Ww + 2 * s);
                d[i][2 * s] = l.x; d[i][2 * s + 1] = l.y;
            }
            d[i][8] = 0.f; d[i][9] = 0.f;
        }
    }

    size_t t0 = (size_t)brow * 32 + qq0;
    #pragma unroll
    for (int a = 0; a < 4; a++) {
        // B^T row transform; a is a compile-time constant after unrolling,
        // so these selects fold to the direct expressions.
        float tm[10];
        #pragma unroll
        for (int jj = 0; jj < 10; jj++) {
            float r;
            if (a == 0)      r = d[0][jj] - d[2][jj];
            else if (a == 1) r = d[1][jj] + d[2][jj];
            else if (a == 2) r = d[2][jj] - d[1][jj];
            else             r = d[1][jj] - d[3][jj];
            tm[jj] = r;
        }

        float v0[4], v1[4], v2[4], v3[4];
        #pragma unroll
        for (int e = 0; e < 4; e++) {
            v0[e] = tm[2 * e + 0] - tm[2 * e + 2];
            v1[e] = tm[2 * e + 1] + tm[2 * e + 2];
            v2[e] = tm[2 * e + 2] - tm[2 * e + 1];
            v3[e] = tm[2 * e + 1] - tm[2 * e + 3];
        }
        __half2* b0 = (__half2*)&g_V16[((size_t)(a * 4 + 0) * Cc + c) * NTP + t0];
        __half2* b1 = (__half2*)&g_V16[((size_t)(a * 4 + 1) * Cc + c) * NTP + t0];
        __half2* b2 = (__half2*)&g_V16[((size_t)(a * 4 + 2) * Cc + c) * NTP + t0];
        __half2* b3 = (__half2*)&g_V16[((size_t)(a * 4 + 3) * Cc + c) * NTP + t0];
        b0[0] = __floats2half2_rn(v0[0], v0[1]); b0[1] = __floats2half2_rn(v0[2], v0[3]);
        b1[0] = __floats2half2_rn(v1[0], v1[1]); b1[1] = __floats2half2_rn(v1[2], v1[3]);
        b2[0] = __floats2half2_rn(v2[0], v2[1]); b2[1] = __floats2half2_rn(v2[2], v2[3]);
        b3[0] = __floats2half2_rn(v3[0], v3[1]); b3[1] = __floats2half2_rn(v3[2], v3[3]);
    }
}

// ---------------------------------------------------------------------------
// 3) fp16 tensor GEMM:  M[k][t] = sum_c U[c][k]*V[c][t], per point p.
//    CTA 128k x 128t, 256 thr, warp 32k x 64t.  32-c chunks, 4 iterations,
//    4-stage cp.async ring (68 KB dynamic smem), 1 sync/chunk.
//    grid = (kb=2 fastest, tb=248, p=16)
// ---------------------------------------------------------------------------
#define PITCH_B 272             /* bytes per smem row (136 halves) */
#define UREG_B  8704            /* 32 rows * 272 */
#define STAGE_B 17408           /* U + V regions */
#define HALF_B  4352            /* 16 rows * 272: second 16-c sub-chunk */

__global__ void __launch_bounds__(256, 2) wino_gemm()
{
    extern __shared__ char smem[];      // 4 * STAGE_B = 69632 B
    const uint32_t sb = smem_u32(smem);

    const int kb = blockIdx.x;          // 0..1
    const int tb = blockIdx.y;          // 0..247
    const int p  = blockIdx.z;          // 0..15

    const int tid  = threadIdx.x;
    const int wid  = tid >> 5, lane = tid & 31;
    const int g    = lane >> 2, tig = lane & 3;
    const int wk   = (wid & 3) * 32;
    const int wt   = (wid >> 2) * 64;

    // ---- loader role: each thread 4 x 16B (64B contiguous) per chunk ------
    const __half* gptr;
    size_t gstep;
    uint32_t soff;
    {
        int id  = (tid & 127) * 4;       // 0..508 step 4
        int row = id >> 4;               // 0..31 (c-row within chunk)
        int seg = id & 15;               // 0,4,8,12 (16B segment within row)
        if (tid < 128) {                 // U: 32 c-rows x 128 k halves
            gptr  = g_U16 + ((size_t)p * Cc + row) * Kk + kb * 128 + seg * 8;
            gstep = (size_t)32 * Kk;
            soff  = (uint32_t)(row * PITCH_B + seg * 16);
        } else {                         // V: 32 c-rows x 128 t halves
            gptr  = g_V16 + ((size_t)p * Cc + row) * NTP + (size_t)tb * 128 + seg * 8;
            gstep = (size_t)32 * NTP;
            soff  = (uint32_t)(UREG_B + row * PITCH_B + seg * 16);
        }
    }

    const uint32_t aoff0 = (uint32_t)(((lane & 7) + ((lane >> 4) & 1) * 8) * PITCH_B
                                      + (wk + ((lane >> 3) & 1) * 8) * 2);
    const uint32_t boff0 = (uint32_t)(UREG_B
                                      + ((lane & 7) + ((lane >> 3) & 1) * 8) * PITCH_B
                                      + (wt + ((lane >> 4) & 1) * 8) * 2);

    float acc[2][8][4];
    #pragma unroll
    for (int mi = 0; mi < 2; mi++)
        #pragma unroll
        for (int nj = 0; nj < 8; nj++)
            #pragma unroll
            for (int q = 0; q < 4; q++)
                acc[mi][nj][q] = 0.0f;

    #pragma unroll
    for (int s = 0; s < 3; s++) {
        uint32_t dst = sb + (uint32_t)s * STAGE_B + soff;
        const __half* src = gptr + (size_t)s * gstep;
        #pragma unroll
        for (int q = 0; q < 4; q++)
            cp16(dst + q * 16, src + q * 8);
        asm volatile("cp.async.commit_group;" ::: "memory");
    }

    #pragma unroll 1
    for (int it = 0; it < 4; it++) {
        asm volatile("cp.async.wait_group %0;" :: "n"(2) : "memory");
        __syncthreads();

        const uint32_t buf = sb + (uint32_t)(it & 3) * STAGE_B;

        #pragma unroll
        for (int h = 0; h < 2; h++) {
            const uint32_t hb = buf + h * HALF_B;
            uint32_t a[2][4];
            ldmx4(a[0], hb + aoff0);
            ldmx4(a[1], hb + aoff0 + 32);
            uint32_t bb[4][4];
            #pragma unroll
            for (int njp = 0; njp < 4; njp++)
                ldmx4(bb[njp], hb + boff0 + njp * 32);

            #pragma unroll
            for (int mi = 0; mi < 2; mi++)
                #pragma unroll
                for (int njp = 0; njp < 4; njp++) {
                    mma_f16(acc[mi][njp * 2 + 0], a[mi], &bb[njp][0]);
                    mma_f16(acc[mi][njp * 2 + 1], a[mi], &bb[njp][2]);
                }
        }

        int nx = it + 3;
        if (nx < 4) {
            uint32_t dst = sb + (uint32_t)(nx & 3) * STAGE_B + soff;
            const __half* src = gptr + (size_t)nx * gstep;
            #pragma unroll
            for (int q = 0; q < 4; q++)
                cp16(dst + q * 16, src + q * 8);
        }
        asm volatile("cp.async.commit_group;" ::: "memory");
    }

    __half* Mp = g_M16 + ((size_t)p * Kk + kb * 128 + wk) * NTP + (size_t)tb * 128 + wt;
    #pragma unroll
    for (int mi = 0; mi < 2; mi++) {
        #pragma unroll
        for (int nj = 0; nj < 8; nj++) {
            int t_off = nj * 8 + 2 * tig;
            __half* r0 = Mp + (size_t)(mi * 16 + g) * NTP + t_off;
            *(__half2*)r0                     = __floats2half2_rn(acc[mi][nj][0], acc[mi][nj][1]);
            *(__half2*)(r0 + (size_t)8 * NTP) = __floats2half2_rn(acc[mi][nj][2], acc[mi][nj][3]);
        }
    }
}

// ---------------------------------------------------------------------------
// 4) Inverse transform + bias, 4 tiles per thread (uint2 M loads).
//    idx range = Kk * (NTP/4) = 2,031,616 = 7936 blocks * 256.
// ---------------------------------------------------------------------------
__global__ void __launch_bounds__(256) out_xform(const float* __restrict__ bias,
                                                 float* __restrict__ out)
{
    unsigned idx = blockIdx.x * blockDim.x + threadIdx.x;
    unsigned k  = idx / (NTP / 4u);
    unsigned tp = idx - k * (NTP / 4u);
    unsigned t  = 4u * tp;
    unsigned qq   = t & 31u;            // 0,4,...,28
    unsigned brow = t >> 5;
    unsigned b    = brow / 31u;
    unsigned pp   = brow - b * 31u;

    float m[4][16];                     // [tile e][p]
    #pragma unroll
    for (int p = 0; p < 16; p++) {
        uint2 r = *(const uint2*)&g_M16[((size_t)p * Kk + k) * NTP + t];
        __half2 h0 = *(__half2*)&r.x, h1 = *(__half2*)&r.y;
        float2 f0 = __half22float2(h0), f1 = __half22float2(h1);
        m[0][p] = f0.x; m[1][p] = f0.y; m[2][p] = f1.x; m[3][p] = f1.y;
    }

    float bv = __ldg(bias + k);

    float y0[4][2], y1[4][2];           // [tile][col] rows 0/1
    #pragma unroll
    for (int e = 0; e < 4; e++) {
        float s0[4], s1[4];
        #pragma unroll
        for (int jj = 0; jj < 4; jj++) {
            s0[jj] = m[e][jj] + m[e][4 + jj] + m[e][8 + jj];
            s1[jj] = m[e][4 + jj] - m[e][8 + jj] - m[e][12 + jj];
        }
        y0[e][0] = s0[0] + s0[1] + s0[2] + bv;
        y0[e][1] = s0[1] - s0[2] - s0[3] + bv;
        y1[e][0] = s1[0] + s1[1] + s1[2] + bv;
        y1[e][1] = s1[1] - s1[2] - s1[3] + bv;
    }

    float* op = out + (((size_t)b * Kk + k) * OH + 2u * pp) * OW + 2u * qq;
    float* oq = op + OW;
    if (qq < 28u) {                      // 4 valid tiles, 8 cols
        *(float4*)op       = make_float4(y0[0][0], y0[0][1], y0[1][0], y0[1][1]);
        *(float4*)(op + 4) = make_float4(y0[2][0], y0[2][1], y0[3][0], y0[3][1]);
        *(float2*)oq       = make_float2(y1[0][0], y1[0][1]);
        *(float4*)(oq + 2) = make_float4(y1[1][0], y1[1][1], y1[2][0], y1[2][1]);
        *(float2*)(oq + 6) = make_float2(y1[3][0], y1[3][1]);
    } else {                             // qq == 28: tiles 28,29,30 valid
        *(float4*)op       = make_float4(y0[0][0], y0[0][1], y0[1][0], y0[1][1]);
        *(float2*)(op + 4) = make_float2(y0[2][0], y0[2][1]);
        *(float2*)oq       = make_float2(y1[0][0], y1[0][1]);
        *(float4*)(oq + 2) = make_float4(y1[1][0], y1[1][1], y1[2][0], y1[2][1]);
    }
}

// ---------------------------------------------------------------------------
extern "C" void kernel_launch(void* const* d_in, const int* in_sizes, int n_in,
                              void* d_out, int out_size)
{
    const float* x    = (const float*)d_in[0];
    const float* w    = (const float*)d_in[1];
    const float* bias = (const float*)d_in[2];
    float* out        = (float*)d_out;

    cudaFuncSetAttribute(wino_gemm, cudaFuncAttributeMaxDynamicSharedMemorySize,
                         4 * STAGE_B);

    filt_xform<<<(Kk * Cc) / 256, 256>>>(w);
    in_xform<<<(Cc * NBR * 8) / 256, 256>>>(x);            // 3968 blocks
    dim3 g3(2, NTP / 128, 16);                             // (kb, tb, p)
    wino_gemm<<<g3, 256, 4 * STAGE_B>>>();
    out_xform<<<(Kk * (NTP / 4)) / 256, 256>>>(bias, out); // 7936 blocks
}

// round 14
// speedup vs baseline: 1.1603x; 1.1603x over previous
#include <cuda_runtime.h>
#include <cuda_fp16.h>
#include <stdint.h>

// ---------------------------------------------------------------------------
// Winograd F(2,3) valid conv, fp16 mma.sync (m16n8k16, fp32 accum):
//   1) xform_fused : filter transform (128 tail blocks) + input transform
//                    V[p][c][t] = B^T d B (fp16, 2 tiles/thread)
//   2) wino_gemm   : M[p][k][t] = sum_c U*V (fp16 HMMA, 16-c chunks, 8 iters,
//                    4-stage cp.async ring; loads issued before compute)
//   3) out_xform   : Y = A^T M A + bias (2 tiles/thread, half2 loads)
// t = (b*31+pp)*32 + qq (qq padded to 32), NTP = 31744.  Pad t-columns are
// never consumed.  This is the round-11 structure (best: 265.7us) with launch
// fusion + gemm prefetch reorder only.
// ---------------------------------------------------------------------------

#define Bn 32
#define Cc 128
#define Hh 64
#define Ww 64
#define Kk 256
#define NBR 992               /* tile rows: 32 b * 31 pp */
#define NTP 31744             /* 992 * 32 = 248 * 128 */
#define OH 62
#define OW 62
#define INX_BLOCKS 7936       /* in_xform part: Cc*NBR*16/256 */

__device__ __half g_U16[16 * Cc * Kk];    //   1 MB  [p][c][k]
__device__ __half g_V16[16 * Cc * NTP];   // 130 MB  [p][c][t]
__device__ __half g_M16[16 * Kk * NTP];   // 260 MB  [p][k][t]

__device__ __forceinline__ uint32_t smem_u32(const void* p) {
    uint32_t a;
    asm("{ .reg .u64 t; cvta.to.shared.u64 t, %1; cvt.u32.u64 %0, t; }" : "=r"(a) : "l"(p));
    return a;
}
__device__ __forceinline__ void cp16(uint32_t dst, const void* src) {
    asm volatile("cp.async.cg.shared.global [%0], [%1], 16;" :: "r"(dst), "l"(src));
}
__device__ __forceinline__ void ldmx4(uint32_t* r, uint32_t addr) {
    asm volatile("ldmatrix.sync.aligned.m8n8.x4.trans.shared.b16 {%0,%1,%2,%3}, [%4];"
                 : "=r"(r[0]), "=r"(r[1]), "=r"(r[2]), "=r"(r[3]) : "r"(addr));
}
__device__ __forceinline__ void mma_f16(float* d, const uint32_t* a, const uint32_t* b) {
    asm volatile(
        "mma.sync.aligned.m16n8k16.row.col.f32.f16.f16.f32 "
        "{%0,%1,%2,%3}, {%4,%5,%6,%7}, {%8,%9}, {%0,%1,%2,%3};"
        : "+f"(d[0]), "+f"(d[1]), "+f"(d[2]), "+f"(d[3])
        : "r"(a[0]), "r"(a[1]), "r"(a[2]), "r"(a[3]), "r"(b[0]), "r"(b[1]));
}

// ---------------------------------------------------------------------------
// 1) Fused transforms.  Blocks [0, INX_BLOCKS): input transform, 2 horizontal
//    tiles/thread (round-11 version).  Blocks [INX_BLOCKS, +128): filter
//    transform U[p][c][k].
// ---------------------------------------------------------------------------
__global__ void __launch_bounds__(256) xform_fused(const float* __restrict__ x,
                                                   const float* __restrict__ w)
{
    if (blockIdx.x >= INX_BLOCKS) {
        // ---------------- filter transform ----------------
        int idx = (blockIdx.x - INX_BLOCKS) * blockDim.x + threadIdx.x;   // 0..32767
        int k = idx >> 7;
        int c = idx & 127;
        const float* g = w + (size_t)(k * Cc + c) * 9;

        float w00 = g[0], w01 = g[1], w02 = g[2];
        float w10 = g[3], w11 = g[4], w12 = g[5];
        float w20 = g[6], w21 = g[7], w22 = g[8];

        float t[4][3];
        t[0][0] = w00;                      t[0][1] = w01;                      t[0][2] = w02;
        t[1][0] = 0.5f * (w00 + w10 + w20); t[1][1] = 0.5f * (w01 + w11 + w21); t[1][2] = 0.5f * (w02 + w12 + w22);
        t[2][0] = 0.5f * (w00 - w10 + w20); t[2][1] = 0.5f * (w01 - w11 + w21); t[2][2] = 0.5f * (w02 - w12 + w22);
        t[3][0] = w20;                      t[3][1] = w21;                      t[3][2] = w22;

        #pragma unroll
        for (int a = 0; a < 4; a++) {
            float u0 = t[a][0];
            float u1 = 0.5f * (t[a][0] + t[a][1] + t[a][2]);
            float u2 = 0.5f * (t[a][0] - t[a][1] + t[a][2]);
            float u3 = t[a][2];
            g_U16[((size_t)(a * 4 + 0) * Cc + c) * Kk + k] = __float2half_rn(u0);
            g_U16[((size_t)(a * 4 + 1) * Cc + c) * Kk + k] = __float2half_rn(u1);
            g_U16[((size_t)(a * 4 + 2) * Cc + c) * Kk + k] = __float2half_rn(u2);
            g_U16[((size_t)(a * 4 + 3) * Cc + c) * Kk + k] = __float2half_rn(u3);
        }
        return;
    }

    // ---------------- input transform (round-11, 2 tiles/thread) ----------
    unsigned idx  = blockIdx.x * blockDim.x + threadIdx.x;
    unsigned j    = idx & 15u;
    unsigned rest = idx >> 4;           // c * 992 + brow
    unsigned c    = rest / NBR;
    unsigned brow = rest - c * NBR;
    unsigned b    = brow / 31u;
    unsigned pp   = brow - b * 31u;
    int qq0 = 2 * j;

    const float* xp = x + (((size_t)(b * Cc + c) * Hh + 2u * pp) * Ww + 2 * qq0);

    float d[4][6];
    if (j < 15) {
        #pragma unroll
        for (int i = 0; i < 4; i++) {
            float2 l0 = *(const float2*)(xp + i * Ww);
            float2 l1 = *(const float2*)(xp + i * Ww + 2);
            float2 l2 = *(const float2*)(xp + i * Ww + 4);
            d[i][0] = l0.x; d[i][1] = l0.y; d[i][2] = l1.x;
            d[i][3] = l1.y; d[i][4] = l2.x; d[i][5] = l2.y;
        }
    } else {
        #pragma unroll
        for (int i = 0; i < 4; i++) {
            float2 l0 = *(const float2*)(xp + i * Ww);
            float2 l1 = *(const float2*)(xp + i * Ww + 2);
            d[i][0] = l0.x; d[i][1] = l0.y; d[i][2] = l1.x;
            d[i][3] = l1.y; d[i][4] = 0.f;  d[i][5] = 0.f;
        }
    }

    float tm[4][6];
    #pragma unroll
    for (int jj = 0; jj < 6; jj++) {
        tm[0][jj] = d[0][jj] - d[2][jj];
        tm[1][jj] = d[1][jj] + d[2][jj];
        tm[2][jj] = d[2][jj] - d[1][jj];
        tm[3][jj] = d[1][jj] - d[3][jj];
    }

    size_t t0 = (size_t)brow * 32 + qq0;
    #pragma unroll
    for (int a = 0; a < 4; a++) {
        float vA0 = tm[a][0] - tm[a][2];
        float vA1 = tm[a][1] + tm[a][2];
        float vA2 = tm[a][2] - tm[a][1];
        float vA3 = tm[a][1] - tm[a][3];
        float vB0 = tm[a][2] - tm[a][4];
        float vB1 = tm[a][3] + tm[a][4];
        float vB2 = tm[a][4] - tm[a][3];
        float vB3 = tm[a][3] - tm[a][5];
        *(__half2*)&g_V16[((size_t)(a * 4 + 0) * Cc + c) * NTP + t0] = __floats2half2_rn(vA0, vB0);
        *(__half2*)&g_V16[((size_t)(a * 4 + 1) * Cc + c) * NTP + t0] = __floats2half2_rn(vA1, vB1);
        *(__half2*)&g_V16[((size_t)(a * 4 + 2) * Cc + c) * NTP + t0] = __floats2half2_rn(vA2, vB2);
        *(__half2*)&g_V16[((size_t)(a * 4 + 3) * Cc + c) * NTP + t0] = __floats2half2_rn(vA3, vB3);
    }
}

// ---------------------------------------------------------------------------
// 2) fp16 tensor GEMM (round-11 structure):  M[k][t] = sum_c U[c][k]*V[c][t]
//    CTA 128k x 128t, 256 thr, warp 32k x 64t, 16-c chunks, 8 iterations,
//    4-stage cp.async ring; NEXT-chunk loads issued BEFORE compute.
//    grid = (kb=2 fastest, tb=248, p=16)
// ---------------------------------------------------------------------------
#define PITCH_B 272             /* bytes per smem row (136 halves) */
#define UREG_B  4352            /* 16 rows * 272 */
#define STAGE_B 8704            /* U + V regions */

__global__ void __launch_bounds__(256, 2) wino_gemm()
{
    __shared__ alignas(16) char smem[4 * STAGE_B];
    const uint32_t sb = smem_u32(smem);

    const int kb = blockIdx.x;          // 0..1
    const int tb = blockIdx.y;          // 0..247
    const int p  = blockIdx.z;          // 0..15

    const int tid  = threadIdx.x;
    const int wid  = tid >> 5, lane = tid & 31;
    const int g    = lane >> 2, tig = lane & 3;
    const int wk   = (wid & 3) * 32;
    const int wt   = (wid >> 2) * 64;

    const __half* gptr;
    size_t gstep;
    uint32_t soff;
    {
        if (tid < 128) {                 // U: 16 c-rows x 128 k halves
            int row = tid >> 3, seg = tid & 7;
            gptr  = g_U16 + ((size_t)p * Cc + row) * Kk + kb * 128 + seg * 8;
            gstep = (size_t)16 * Kk;
            soff  = (uint32_t)(row * PITCH_B + seg * 16);
        } else {                         // V: 16 c-rows x 128 t halves
            int jj = tid - 128;
            int row = jj >> 3, seg = jj & 7;
            gptr  = g_V16 + ((size_t)p * Cc + row) * NTP + (size_t)tb * 128 + seg * 8;
            gstep = (size_t)16 * NTP;
            soff  = (uint32_t)(UREG_B + row * PITCH_B + seg * 16);
        }
    }

    const uint32_t aoff0 = (uint32_t)(((lane & 7) + ((lane >> 4) & 1) * 8) * PITCH_B
                                      + (wk + ((lane >> 3) & 1) * 8) * 2);
    const uint32_t boff0 = (uint32_t)(UREG_B
                                      + ((lane & 7) + ((lane >> 3) & 1) * 8) * PITCH_B
                                      + (wt + ((lane >> 4) & 1) * 8) * 2);

    float acc[2][8][4];
    #pragma unroll
    for (int mi = 0; mi < 2; mi++)
        #pragma unroll
        for (int nj = 0; nj < 8; nj++)
            #pragma unroll
            for (int q = 0; q < 4; q++)
                acc[mi][nj][q] = 0.0f;

    #pragma unroll
    for (int s = 0; s < 3; s++) {
        uint32_t dst = sb + (uint32_t)s * STAGE_B + soff;
        cp16(dst,       gptr + (size_t)s * gstep);
        cp16(dst + 128, gptr + (size_t)s * gstep + 64);
        asm volatile("cp.async.commit_group;" ::: "memory");
    }

    #pragma unroll 1
    for (int it = 0; it < 8; it++) {
        asm volatile("cp.async.wait_group %0;" :: "n"(2) : "memory");
        __syncthreads();

        // issue next-chunk loads FIRST: buffer (it+3)&3 was freed by the sync
        int nx = it + 3;
        if (nx < 8) {
            uint32_t dst = sb + (uint32_t)(nx & 3) * STAGE_B + soff;
            cp16(dst,       gptr + (size_t)nx * gstep);
            cp16(dst + 128, gptr + (size_t)nx * gstep + 64);
        }
        asm volatile("cp.async.commit_group;" ::: "memory");

        const uint32_t buf = sb + (uint32_t)(it & 3) * STAGE_B;

        uint32_t a[2][4];
        ldmx4(a[0], buf + aoff0);
        ldmx4(a[1], buf + aoff0 + 32);
        uint32_t bb[4][4];
        #pragma unroll
        for (int njp = 0; njp < 4; njp++)
            ldmx4(bb[njp], buf + boff0 + njp * 32);

        #pragma unroll
        for (int mi = 0; mi < 2; mi++)
            #pragma unroll
            for (int njp = 0; njp < 4; njp++) {
                mma_f16(acc[mi][njp * 2 + 0], a[mi], &bb[njp][0]);
                mma_f16(acc[mi][njp * 2 + 1], a[mi], &bb[njp][2]);
            }
    }

    __half* Mp = g_M16 + ((size_t)p * Kk + kb * 128 + wk) * NTP + (size_t)tb * 128 + wt;
    #pragma unroll
    for (int mi = 0; mi < 2; mi++) {
        #pragma unroll
        for (int nj = 0; nj < 8; nj++) {
            int t_off = nj * 8 + 2 * tig;
            __half* r0 = Mp + (size_t)(mi * 16 + g) * NTP + t_off;
            *(__half2*)r0                     = __floats2half2_rn(acc[mi][nj][0], acc[mi][nj][1]);
            *(__half2*)(r0 + (size_t)8 * NTP) = __floats2half2_rn(acc[mi][nj][2], acc[mi][nj][3]);
        }
    }
}

// ---------------------------------------------------------------------------
// 3) Inverse transform + bias, 2 tiles per thread (round-11 version).
// ---------------------------------------------------------------------------
__global__ void __launch_bounds__(256) out_xform(const float* __restrict__ bias,
                                                 float* __restrict__ out)
{
    unsigned idx = blockIdx.x * blockDim.x + threadIdx.x;
    unsigned k  = idx / (NTP / 2u);
    unsigned tp = idx - k * (NTP / 2u);
    unsigned t  = 2u * tp;
    unsigned qq   = t & 31u;
    unsigned brow = t >> 5;
    unsigned b    = brow / 31u;
    unsigned pp   = brow - b * 31u;

    float mA[16], mB[16];
    #pragma unroll
    for (int p = 0; p < 16; p++) {
        __half2 h = *(const __half2*)&g_M16[((size_t)p * Kk + k) * NTP + t];
        float2 f = __half22float2(h);
        mA[p] = f.x; mB[p] = f.y;
    }

    float bv = __ldg(bias + k);

    float sA0[4], sA1[4], sB0[4], sB1[4];
    #pragma unroll
    for (int jj = 0; jj < 4; jj++) {
        sA0[jj] = mA[jj] + mA[4 + jj] + mA[8 + jj];
        sA1[jj] = mA[4 + jj] - mA[8 + jj] - mA[12 + jj];
        sB0[jj] = mB[jj] + mB[4 + jj] + mB[8 + jj];
        sB1[jj] = mB[4 + jj] - mB[8 + jj] - mB[12 + jj];
    }
    float yA00 = sA0[0] + sA0[1] + sA0[2] + bv;
    float yA01 = sA0[1] - sA0[2] - sA0[3] + bv;
    float yA10 = sA1[0] + sA1[1] + sA1[2] + bv;
    float yA11 = sA1[1] - sA1[2] - sA1[3] + bv;
    float yB00 = sB0[0] + sB0[1] + sB0[2] + bv;
    float yB01 = sB0[1] - sB0[2] - sB0[3] + bv;
    float yB10 = sB1[0] + sB1[1] + sB1[2] + bv;
    float yB11 = sB1[1] - sB1[2] - sB1[3] + bv;

    float* op = out + (((size_t)b * Kk + k) * OH + 2u * pp) * OW + 2u * qq;
    if (qq < 30u) {
        *(float4*)op = make_float4(yA00, yA01, yB00, yB01);
        *(float2*)(op + OW)     = make_float2(yA10, yA11);
        *(float2*)(op + OW + 2) = make_float2(yB10, yB11);
    } else {                       // qq == 30: second tile is pad
        *(float2*)op        = make_float2(yA00, yA01);
        *(float2*)(op + OW) = make_float2(yA10, yA11);
    }
}

// ---------------------------------------------------------------------------
extern "C" void kernel_launch(void* const* d_in, const int* in_sizes, int n_in,
                              void* d_out, int out_size)
{
    const float* x    = (const float*)d_in[0];
    const float* w    = (const float*)d_in[1];
    const float* bias = (const float*)d_in[2];
    float* out        = (float*)d_out;

    xform_fused<<<INX_BLOCKS + 128, 256>>>(x, w);          // 8064 blocks
    dim3 g3(2, NTP / 128, 16);                             // (kb, tb, p)
    wino_gemm<<<g3, 256>>>();
    out_xform<<<(Kk * (NTP / 2)) / 256, 256>>>(bias, out); // 15872 blocks
}

// round 15
// speedup vs baseline: 1.1632x; 1.0025x over previous
#include <cuda_runtime.h>
#include <cuda_fp16.h>
#include <stdint.h>

// ---------------------------------------------------------------------------
// Winograd F(2,3) valid conv, fp16 mma.sync (m16n8k16, fp32 accum):
//   1) filt_xform : U[p][c][k] = G g G^T   (fp16, k-fastest lanes -> coalesced)
//   2) in_xform   : V[p][c][t] = B^T d B   (fp16, 4 tiles/thread)
//   3) wino_gemm  : M[p][k][t] = sum_c U*V (fp16 HMMA; round-11 exact)
//   4) out_xform  : Y = A^T M A + bias     (2 tiles/thread; round-11 exact)
// t = (b*31+pp)*32 + qq (qq padded to 32), NTP = 31744.  Pad t-columns are
// never consumed.
// ---------------------------------------------------------------------------

#define Bn 32
#define Cc 128
#define Hh 64
#define Ww 64
#define Kk 256
#define NBR 992               /* tile rows: 32 b * 31 pp */
#define NTP 31744             /* 992 * 32 = 248 * 128 */
#define OH 62
#define OW 62

__device__ __half g_U16[16 * Cc * Kk];    //   1 MB  [p][c][k]
__device__ __half g_V16[16 * Cc * NTP];   // 130 MB  [p][c][t]
__device__ __half g_M16[16 * Kk * NTP];   // 260 MB  [p][k][t]

__device__ __forceinline__ uint32_t smem_u32(const void* p) {
    uint32_t a;
    asm("{ .reg .u64 t; cvta.to.shared.u64 t, %1; cvt.u32.u64 %0, t; }" : "=r"(a) : "l"(p));
    return a;
}
__device__ __forceinline__ void cp16(uint32_t dst, const void* src) {
    asm volatile("cp.async.cg.shared.global [%0], [%1], 16;" :: "r"(dst), "l"(src));
}
__device__ __forceinline__ void ldmx4(uint32_t* r, uint32_t addr) {
    asm volatile("ldmatrix.sync.aligned.m8n8.x4.trans.shared.b16 {%0,%1,%2,%3}, [%4];"
                 : "=r"(r[0]), "=r"(r[1]), "=r"(r[2]), "=r"(r[3]) : "r"(addr));
}
__device__ __forceinline__ void mma_f16(float* d, const uint32_t* a, const uint32_t* b) {
    asm volatile(
        "mma.sync.aligned.m16n8k16.row.col.f32.f16.f16.f32 "
        "{%0,%1,%2,%3}, {%4,%5,%6,%7}, {%8,%9}, {%0,%1,%2,%3};"
        : "+f"(d[0]), "+f"(d[1]), "+f"(d[2]), "+f"(d[3])
        : "r"(a[0]), "r"(a[1]), "r"(a[2]), "r"(a[3]), "r"(b[0]), "r"(b[1]));
}

// ---------------------------------------------------------------------------
// 1) Filter transform -> U[p][c][k] fp16.  Lanes map to consecutive k, so
//    each plane store is 64 B contiguous per warp (was 2 B x 512 B stride).
// ---------------------------------------------------------------------------
__global__ void filt_xform(const float* __restrict__ w)
{
    int idx = blockIdx.x * blockDim.x + threadIdx.x;   // 32768
    int k = idx & 255;          // k fastest across lanes
    int c = idx >> 8;
    const float* g = w + (size_t)(k * Cc + c) * 9;

    float w00 = g[0], w01 = g[1], w02 = g[2];
    float w10 = g[3], w11 = g[4], w12 = g[5];
    float w20 = g[6], w21 = g[7], w22 = g[8];

    float t[4][3];
    t[0][0] = w00;                      t[0][1] = w01;                      t[0][2] = w02;
    t[1][0] = 0.5f * (w00 + w10 + w20); t[1][1] = 0.5f * (w01 + w11 + w21); t[1][2] = 0.5f * (w02 + w12 + w22);
    t[2][0] = 0.5f * (w00 - w10 + w20); t[2][1] = 0.5f * (w01 - w11 + w21); t[2][2] = 0.5f * (w02 - w12 + w22);
    t[3][0] = w20;                      t[3][1] = w21;                      t[3][2] = w22;

    #pragma unroll
    for (int a = 0; a < 4; a++) {
        float u0 = t[a][0];
        float u1 = 0.5f * (t[a][0] + t[a][1] + t[a][2]);
        float u2 = 0.5f * (t[a][0] - t[a][1] + t[a][2]);
        float u3 = t[a][2];
        g_U16[((size_t)(a * 4 + 0) * Cc + c) * Kk + k] = __float2half_rn(u0);
        g_U16[((size_t)(a * 4 + 1) * Cc + c) * Kk + k] = __float2half_rn(u1);
        g_U16[((size_t)(a * 4 + 2) * Cc + c) * Kk + k] = __float2half_rn(u2);
        g_U16[((size_t)(a * 4 + 3) * Cc + c) * Kk + k] = __float2half_rn(u3);
    }
}

// ---------------------------------------------------------------------------
// 2) Input transform -> V[p][c][t], 4 horizontal tiles per thread (round-13
//    version, verified bit-identical rel_err).  Thread (c, brow, j): tiles
//    qq = 4j..4j+3; j==7 -> tiles 28,29,30 (+pad written, never read).
//    idx range = 128 * 992 * 8 = 1,015,808 = 3968 blocks * 256.
// ---------------------------------------------------------------------------
__global__ void __launch_bounds__(256) in_xform(const float* __restrict__ x)
{
    unsigned idx  = blockIdx.x * blockDim.x + threadIdx.x;
    unsigned j    = idx & 7u;
    unsigned rest = idx >> 3;           // c * 992 + brow
    unsigned c    = rest / NBR;
    unsigned brow = rest - c * NBR;
    unsigned b    = brow / 31u;
    unsigned pp   = brow - b * 31u;
    int qq0 = 4 * j;

    const float* xp = x + (((size_t)(b * Cc + c) * Hh + 2u * pp) * Ww + 2 * qq0);

    float d[4][10];
    if (j < 7) {
        #pragma unroll
        for (int i = 0; i < 4; i++) {
            #pragma unroll
            for (int s = 0; s < 5; s++) {
                float2 l = *(const float2*)(xp + i * Ww + 2 * s);
                d[i][2 * s] = l.x; d[i][2 * s + 1] = l.y;
            }
        }
    } else {                             // cols 56..63 only; 64,65 OOB -> 0
        #pragma unroll
        for (int i = 0; i < 4; i++) {
            #pragma unroll
            for (int s = 0; s < 4; s++) {
                float2 l = *(const float2*)(xp + i * Ww + 2 * s);
                d[i][2 * s] = l.x; d[i][2 * s + 1] = l.y;
            }
            d[i][8] = 0.f; d[i][9] = 0.f;
        }
    }

    size_t t0 = (size_t)brow * 32 + qq0;
    #pragma unroll
    for (int a = 0; a < 4; a++) {
        float tm[10];
        #pragma unroll
        for (int jj = 0; jj < 10; jj++) {
            float r;
            if (a == 0)      r = d[0][jj] - d[2][jj];
            else if (a == 1) r = d[1][jj] + d[2][jj];
            else if (a == 2) r = d[2][jj] - d[1][jj];
            else             r = d[1][jj] - d[3][jj];
            tm[jj] = r;
        }

        float v0[4], v1[4], v2[4], v3[4];
        #pragma unroll
        for (int e = 0; e < 4; e++) {
            v0[e] = tm[2 * e + 0] - tm[2 * e + 2];
            v1[e] = tm[2 * e + 1] + tm[2 * e + 2];
            v2[e] = tm[2 * e + 2] - tm[2 * e + 1];
            v3[e] = tm[2 * e + 1] - tm[2 * e + 3];
        }
        __half2* b0 = (__half2*)&g_V16[((size_t)(a * 4 + 0) * Cc + c) * NTP + t0];
        __half2* b1 = (__half2*)&g_V16[((size_t)(a * 4 + 1) * Cc + c) * NTP + t0];
        __half2* b2 = (__half2*)&g_V16[((size_t)(a * 4 + 2) * Cc + c) * NTP + t0];
        __half2* b3 = (__half2*)&g_V16[((size_t)(a * 4 + 3) * Cc + c) * NTP + t0];
        b0[0] = __floats2half2_rn(v0[0], v0[1]); b0[1] = __floats2half2_rn(v0[2], v0[3]);
        b1[0] = __floats2half2_rn(v1[0], v1[1]); b1[1] = __floats2half2_rn(v1[2], v1[3]);
        b2[0] = __floats2half2_rn(v2[0], v2[1]); b2[1] = __floats2half2_rn(v2[2], v2[3]);
        b3[0] = __floats2half2_rn(v3[0], v3[1]); b3[1] = __floats2half2_rn(v3[2], v3[3]);
    }
}

// ---------------------------------------------------------------------------
// 3) fp16 tensor GEMM (round-11 EXACT):  M[k][t] = sum_c U[c][k]*V[c][t].
//    CTA 128k x 128t, 256 thr, warp 32k x 64t, 16-c chunks, 8 iterations,
//    4-stage cp.async ring, prefetch issued after compute.
//    grid = (kb=2 fastest, tb=248, p=16)
// ---------------------------------------------------------------------------
#define PITCH_B 272             /* bytes per smem row (136 halves) */
#define UREG_B  4352            /* 16 rows * 272 */
#define STAGE_B 8704            /* U + V regions */

__global__ void __launch_bounds__(256, 2) wino_gemm()
{
    __shared__ alignas(16) char smem[4 * STAGE_B];
    const uint32_t sb = smem_u32(smem);

    const int kb = blockIdx.x;          // 0..1
    const int tb = blockIdx.y;          // 0..247
    const int p  = blockIdx.z;          // 0..15

    const int tid  = threadIdx.x;
    const int wid  = tid >> 5, lane = tid & 31;
    const int g    = lane >> 2, tig = lane & 3;
    const int wk   = (wid & 3) * 32;
    const int wt   = (wid >> 2) * 64;

    const __half* gptr;
    size_t gstep;
    uint32_t soff;
    {
        if (tid < 128) {                 // U: 16 c-rows x 128 k halves
            int row = tid >> 3, seg = tid & 7;
            gptr  = g_U16 + ((size_t)p * Cc + row) * Kk + kb * 128 + seg * 8;
            gstep = (size_t)16 * Kk;
            soff  = (uint32_t)(row * PITCH_B + seg * 16);
        } else {                         // V: 16 c-rows x 128 t halves
            int jj = tid - 128;
            int row = jj >> 3, seg = jj & 7;
            gptr  = g_V16 + ((size_t)p * Cc + row) * NTP + (size_t)tb * 128 + seg * 8;
            gstep = (size_t)16 * NTP;
            soff  = (uint32_t)(UREG_B + row * PITCH_B + seg * 16);
        }
    }

    const uint32_t aoff0 = (uint32_t)(((lane & 7) + ((lane >> 4) & 1) * 8) * PITCH_B
                                      + (wk + ((lane >> 3) & 1) * 8) * 2);
    const uint32_t boff0 = (uint32_t)(UREG_B
                                      + ((lane & 7) + ((lane >> 3) & 1) * 8) * PITCH_B
                                      + (wt + ((lane >> 4) & 1) * 8) * 2);

    float acc[2][8][4];
    #pragma unroll
    for (int mi = 0; mi < 2; mi++)
        #pragma unroll
        for (int nj = 0; nj < 8; nj++)
            #pragma unroll
            for (int q = 0; q < 4; q++)
                acc[mi][nj][q] = 0.0f;

    #pragma unroll
    for (int s = 0; s < 3; s++) {
        uint32_t dst = sb + (uint32_t)s * STAGE_B + soff;
        cp16(dst,       gptr + (size_t)s * gstep);
        cp16(dst + 128, gptr + (size_t)s * gstep + 64);
        asm volatile("cp.async.commit_group;" ::: "memory");
    }

    #pragma unroll 1
    for (int it = 0; it < 8; it++) {
        asm volatile("cp.async.wait_group %0;" :: "n"(2) : "memory");
        __syncthreads();

        const uint32_t buf = sb + (uint32_t)(it & 3) * STAGE_B;

        uint32_t a[2][4];
        ldmx4(a[0], buf + aoff0);
        ldmx4(a[1], buf + aoff0 + 32);
        uint32_t bb[4][4];
        #pragma unroll
        for (int njp = 0; njp < 4; njp++)
            ldmx4(bb[njp], buf + boff0 + njp * 32);

        #pragma unroll
        for (int mi = 0; mi < 2; mi++)
            #pragma unroll
            for (int njp = 0; njp < 4; njp++) {
                mma_f16(acc[mi][njp * 2 + 0], a[mi], &bb[njp][0]);
                mma_f16(acc[mi][njp * 2 + 1], a[mi], &bb[njp][2]);
            }

        int nx = it + 3;
        if (nx < 8) {
            uint32_t dst = sb + (uint32_t)(nx & 3) * STAGE_B + soff;
            cp16(dst,       gptr + (size_t)nx * gstep);
            cp16(dst + 128, gptr + (size_t)nx * gstep + 64);
        }
        asm volatile("cp.async.commit_group;" ::: "memory");
    }

    __half* Mp = g_M16 + ((size_t)p * Kk + kb * 128 + wk) * NTP + (size_t)tb * 128 + wt;
    #pragma unroll
    for (int mi = 0; mi < 2; mi++) {
        #pragma unroll
        for (int nj = 0; nj < 8; nj++) {
            int t_off = nj * 8 + 2 * tig;
            __half* r0 = Mp + (size_t)(mi * 16 + g) * NTP + t_off;
            *(__half2*)r0                     = __floats2half2_rn(acc[mi][nj][0], acc[mi][nj][1]);
            *(__half2*)(r0 + (size_t)8 * NTP) = __floats2half2_rn(acc[mi][nj][2], acc[mi][nj][3]);
        }
    }
}

// ---------------------------------------------------------------------------
// 4) Inverse transform + bias, 2 tiles per thread (round-11 EXACT).
// ---------------------------------------------------------------------------
__global__ void __launch_bounds__(256) out_xform(const float* __restrict__ bias,
                                                 float* __restrict__ out)
{
    unsigned idx = blockIdx.x * blockDim.x + threadIdx.x;
    unsigned k  = idx / (NTP / 2u);
    unsigned tp = idx - k * (NTP / 2u);
    unsigned t  = 2u * tp;
    unsigned qq   = t & 31u;
    unsigned brow = t >> 5;
    unsigned b    = brow / 31u;
    unsigned pp   = brow - b * 31u;

    float mA[16], mB[16];
    #pragma unroll
    for (int p = 0; p < 16; p++) {
        __half2 h = *(const __half2*)&g_M16[((size_t)p * Kk + k) * NTP + t];
        float2 f = __half22float2(h);
        mA[p] = f.x; mB[p] = f.y;
    }

    float bv = __ldg(bias + k);

    float sA0[4], sA1[4], sB0[4], sB1[4];
    #pragma unroll
    for (int jj = 0; jj < 4; jj++) {
        sA0[jj] = mA[jj] + mA[4 + jj] + mA[8 + jj];
        sA1[jj] = mA[4 + jj] - mA[8 + jj] - mA[12 + jj];
        sB0[jj] = mB[jj] + mB[4 + jj] + mB[8 + jj];
        sB1[jj] = mB[4 + jj] - mB[8 + jj] - mB[12 + jj];
    }
    float yA00 = sA0[0] + sA0[1] + sA0[2] + bv;
    float yA01 = sA0[1] - sA0[2] - sA0[3] + bv;
    float yA10 = sA1[0] + sA1[1] + sA1[2] + bv;
    float yA11 = sA1[1] - sA1[2] - sA1[3] + bv;
    float yB00 = sB0[0] + sB0[1] + sB0[2] + bv;
    float yB01 = sB0[1] - sB0[2] - sB0[3] + bv;
    float yB10 = sB1[0] + sB1[1] + sB1[2] + bv;
    float yB11 = sB1[1] - sB1[2] - sB1[3] + bv;

    float* op = out + (((size_t)b * Kk + k) * OH + 2u * pp) * OW + 2u * qq;
    if (qq < 30u) {
        *(float4*)op = make_float4(yA00, yA01, yB00, yB01);
        *(float2*)(op + OW)     = make_float2(yA10, yA11);
        *(float2*)(op + OW + 2) = make_float2(yB10, yB11);
    } else {                       // qq == 30: second tile is pad
        *(float2*)op        = make_float2(yA00, yA01);
        *(float2*)(op + OW) = make_float2(yA10, yA11);
    }
}

// ---------------------------------------------------------------------------
extern "C" void kernel_launch(void* const* d_in, const int* in_sizes, int n_in,
                              void* d_out, int out_size)
{
    const float* x    = (const float*)d_in[0];
    const float* w    = (const float*)d_in[1];
    const float* bias = (const float*)d_in[2];
    float* out        = (float*)d_out;

    filt_xform<<<(Kk * Cc) / 256, 256>>>(w);
    in_xform<<<(Cc * NBR * 8) / 256, 256>>>(x);            // 3968 blocks
    dim3 g3(2, NTP / 128, 16);                             // (kb, tb, p)
    wino_gemm<<<g3, 256>>>();
    out_xform<<<(Kk * (NTP / 2)) / 256, 256>>>(bias, out); // 15872 blocks
}

// round 16
// speedup vs baseline: 1.1849x; 1.0186x over previous
#include <cuda_runtime.h>
#include <cuda_fp16.h>
#include <stdint.h>

// ---------------------------------------------------------------------------
// Winograd F(2,3) valid conv, fp16 mma.sync (m16n8k16, fp32 accum):
//   1) filt_xform : U[p][c][k] = G g G^T   (fp16)
//   2) in_xform   : V[p][c][t] = B^T d B   (fp16, 2 tiles/thread)
//   3) wino_gemm  : M[p][k][t] = sum_c U*V (fp16 HMMA, fp32 acc, fp16 M)
//   4) out_xform  : Y = A^T M A + bias     (2 tiles/thread, half2 loads)
// t = (b*31+pp)*32 + qq (qq padded to 32), NTP = 31744.  Pad t-columns are
// never consumed.  This is the measured-best configuration (round 11).
// ---------------------------------------------------------------------------

#define Bn 32
#define Cc 128
#define Hh 64
#define Ww 64
#define Kk 256
#define NBR 992               /* tile rows: 32 b * 31 pp */
#define NTP 31744             /* 992 * 32 = 248 * 128 */
#define OH 62
#define OW 62

__device__ __half g_U16[16 * Cc * Kk];    //   1 MB  [p][c][k]
__device__ __half g_V16[16 * Cc * NTP];   // 130 MB  [p][c][t]
__device__ __half g_M16[16 * Kk * NTP];   // 260 MB  [p][k][t]

__device__ __forceinline__ uint32_t smem_u32(const void* p) {
    uint32_t a;
    asm("{ .reg .u64 t; cvta.to.shared.u64 t, %1; cvt.u32.u64 %0, t; }" : "=r"(a) : "l"(p));
    return a;
}
__device__ __forceinline__ void cp16(uint32_t dst, const void* src) {
    asm volatile("cp.async.cg.shared.global [%0], [%1], 16;" :: "r"(dst), "l"(src));
}
__device__ __forceinline__ void ldmx4(uint32_t* r, uint32_t addr) {
    asm volatile("ldmatrix.sync.aligned.m8n8.x4.trans.shared.b16 {%0,%1,%2,%3}, [%4];"
                 : "=r"(r[0]), "=r"(r[1]), "=r"(r[2]), "=r"(r[3]) : "r"(addr));
}
__device__ __forceinline__ void mma_f16(float* d, const uint32_t* a, const uint32_t* b) {
    asm volatile(
        "mma.sync.aligned.m16n8k16.row.col.f32.f16.f16.f32 "
        "{%0,%1,%2,%3}, {%4,%5,%6,%7}, {%8,%9}, {%0,%1,%2,%3};"
        : "+f"(d[0]), "+f"(d[1]), "+f"(d[2]), "+f"(d[3])
        : "r"(a[0]), "r"(a[1]), "r"(a[2]), "r"(a[3]), "r"(b[0]), "r"(b[1]));
}

// ---------------------------------------------------------------------------
// 1) Filter transform -> U[p][c][k] fp16
// ---------------------------------------------------------------------------
__global__ void filt_xform(const float* __restrict__ w)
{
    int idx = blockIdx.x * blockDim.x + threadIdx.x;   // 32768
    int k = idx >> 7;
    int c = idx & 127;
    const float* g = w + (size_t)(k * Cc + c) * 9;

    float w00 = g[0], w01 = g[1], w02 = g[2];
    float w10 = g[3], w11 = g[4], w12 = g[5];
    float w20 = g[6], w21 = g[7], w22 = g[8];

    float t[4][3];
    t[0][0] = w00;                      t[0][1] = w01;                      t[0][2] = w02;
    t[1][0] = 0.5f * (w00 + w10 + w20); t[1][1] = 0.5f * (w01 + w11 + w21); t[1][2] = 0.5f * (w02 + w12 + w22);
    t[2][0] = 0.5f * (w00 - w10 + w20); t[2][1] = 0.5f * (w01 - w11 + w21); t[2][2] = 0.5f * (w02 - w12 + w22);
    t[3][0] = w20;                      t[3][1] = w21;                      t[3][2] = w22;

    #pragma unroll
    for (int a = 0; a < 4; a++) {
        float u0 = t[a][0];
        float u1 = 0.5f * (t[a][0] + t[a][1] + t[a][2]);
        float u2 = 0.5f * (t[a][0] - t[a][1] + t[a][2]);
        float u3 = t[a][2];
        g_U16[((size_t)(a * 4 + 0) * Cc + c) * Kk + k] = __float2half_rn(u0);
        g_U16[((size_t)(a * 4 + 1) * Cc + c) * Kk + k] = __float2half_rn(u1);
        g_U16[((size_t)(a * 4 + 2) * Cc + c) * Kk + k] = __float2half_rn(u2);
        g_U16[((size_t)(a * 4 + 3) * Cc + c) * Kk + k] = __float2half_rn(u3);
    }
}

// ---------------------------------------------------------------------------
// 2) Input transform -> V[p][c][t], 2 horizontal tiles per thread.
//    Thread (c, brow, j): tiles qq = 2j, 2j+1 (j==15: only qq=30).
//    idx range = 128 * 992 * 16 = 2,031,616 = 7936 blocks * 256.
// ---------------------------------------------------------------------------
__global__ void __launch_bounds__(256) in_xform(const float* __restrict__ x)
{
    unsigned idx  = blockIdx.x * blockDim.x + threadIdx.x;
    unsigned j    = idx & 15u;
    unsigned rest = idx >> 4;           // c * 992 + brow
    unsigned c    = rest / NBR;
    unsigned brow = rest - c * NBR;
    unsigned b    = brow / 31u;
    unsigned pp   = brow - b * 31u;
    int qq0 = 2 * j;

    const float* xp = x + (((size_t)(b * Cc + c) * Hh + 2u * pp) * Ww + 2 * qq0);

    float d[4][6];
    if (j < 15) {
        #pragma unroll
        for (int i = 0; i < 4; i++) {
            float2 l0 = *(const float2*)(xp + i * Ww);
            float2 l1 = *(const float2*)(xp + i * Ww + 2);
            float2 l2 = *(const float2*)(xp + i * Ww + 4);
            d[i][0] = l0.x; d[i][1] = l0.y; d[i][2] = l1.x;
            d[i][3] = l1.y; d[i][4] = l2.x; d[i][5] = l2.y;
        }
    } else {
        #pragma unroll
        for (int i = 0; i < 4; i++) {
            float2 l0 = *(const float2*)(xp + i * Ww);
            float2 l1 = *(const float2*)(xp + i * Ww + 2);
            d[i][0] = l0.x; d[i][1] = l0.y; d[i][2] = l1.x;
            d[i][3] = l1.y; d[i][4] = 0.f;  d[i][5] = 0.f;
        }
    }

    float tm[4][6];
    #pragma unroll
    for (int jj = 0; jj < 6; jj++) {
        tm[0][jj] = d[0][jj] - d[2][jj];
        tm[1][jj] = d[1][jj] + d[2][jj];
        tm[2][jj] = d[2][jj] - d[1][jj];
        tm[3][jj] = d[1][jj] - d[3][jj];
    }

    size_t t0 = (size_t)brow * 32 + qq0;
    #pragma unroll
    for (int a = 0; a < 4; a++) {
        float vA0 = tm[a][0] - tm[a][2];
        float vA1 = tm[a][1] + tm[a][2];
        float vA2 = tm[a][2] - tm[a][1];
        float vA3 = tm[a][1] - tm[a][3];
        float vB0 = tm[a][2] - tm[a][4];
        float vB1 = tm[a][3] + tm[a][4];
        float vB2 = tm[a][4] - tm[a][3];
        float vB3 = tm[a][3] - tm[a][5];
        *(__half2*)&g_V16[((size_t)(a * 4 + 0) * Cc + c) * NTP + t0] = __floats2half2_rn(vA0, vB0);
        *(__half2*)&g_V16[((size_t)(a * 4 + 1) * Cc + c) * NTP + t0] = __floats2half2_rn(vA1, vB1);
        *(__half2*)&g_V16[((size_t)(a * 4 + 2) * Cc + c) * NTP + t0] = __floats2half2_rn(vA2, vB2);
        *(__half2*)&g_V16[((size_t)(a * 4 + 3) * Cc + c) * NTP + t0] = __floats2half2_rn(vA3, vB3);
    }
}

// ---------------------------------------------------------------------------
// 3) fp16 tensor GEMM:  M[k][t] = sum_c U[c][k]*V[c][t], per point p.
//    CTA 128k x 128t, 256 thr, warp 32k x 64t, 16-c chunks, 8 iterations,
//    4-stage cp.async ring, 1 sync/chunk, ldmatrix.x4.trans.
//    grid = (kb=2 fastest, tb=248, p=16)
// ---------------------------------------------------------------------------
#define PITCH_B 272             /* bytes per smem row (136 halves) */
#define UREG_B  4352            /* 16 rows * 272 */
#define STAGE_B 8704            /* U + V regions */

__global__ void __launch_bounds__(256, 2) wino_gemm()
{
    __shared__ alignas(16) char smem[4 * STAGE_B];
    const uint32_t sb = smem_u32(smem);

    const int kb = blockIdx.x;          // 0..1
    const int tb = blockIdx.y;          // 0..247
    const int p  = blockIdx.z;          // 0..15

    const int tid  = threadIdx.x;
    const int wid  = tid >> 5, lane = tid & 31;
    const int g    = lane >> 2, tig = lane & 3;
    const int wk   = (wid & 3) * 32;
    const int wt   = (wid >> 2) * 64;

    const __half* gptr;
    size_t gstep;
    uint32_t soff;
    {
        if (tid < 128) {                 // U: 16 c-rows x 128 k halves
            int row = tid >> 3, seg = tid & 7;
            gptr  = g_U16 + ((size_t)p * Cc + row) * Kk + kb * 128 + seg * 8;
            gstep = (size_t)16 * Kk;
            soff  = (uint32_t)(row * PITCH_B + seg * 16);
        } else {                         // V: 16 c-rows x 128 t halves
            int jj = tid - 128;
            int row = jj >> 3, seg = jj & 7;
            gptr  = g_V16 + ((size_t)p * Cc + row) * NTP + (size_t)tb * 128 + seg * 8;
            gstep = (size_t)16 * NTP;
            soff  = (uint32_t)(UREG_B + row * PITCH_B + seg * 16);
        }
    }

    const uint32_t aoff0 = (uint32_t)(((lane & 7) + ((lane >> 4) & 1) * 8) * PITCH_B
                                      + (wk + ((lane >> 3) & 1) * 8) * 2);
    const uint32_t boff0 = (uint32_t)(UREG_B
                                      + ((lane & 7) + ((lane >> 3) & 1) * 8) * PITCH_B
                                      + (wt + ((lane >> 4) & 1) * 8) * 2);

    float acc[2][8][4];
    #pragma unroll
    for (int mi = 0; mi < 2; mi++)
        #pragma unroll
        for (int nj = 0; nj < 8; nj++)
            #pragma unroll
            for (int q = 0; q < 4; q++)
                acc[mi][nj][q] = 0.0f;

    #pragma unroll
    for (int s = 0; s < 3; s++) {
        uint32_t dst = sb + (uint32_t)s * STAGE_B + soff;
        cp16(dst,       gptr + (size_t)s * gstep);
        cp16(dst + 128, gptr + (size_t)s * gstep + 64);
        asm volatile("cp.async.commit_group;" ::: "memory");
    }

    #pragma unroll 1
    for (int it = 0; it < 8; it++) {
        asm volatile("cp.async.wait_group %0;" :: "n"(2) : "memory");
        __syncthreads();

        const uint32_t buf = sb + (uint32_t)(it & 3) * STAGE_B;

        uint32_t a[2][4];
        ldmx4(a[0], buf + aoff0);
        ldmx4(a[1], buf + aoff0 + 32);
        uint32_t bb[4][4];
        #pragma unroll
        for (int njp = 0; njp < 4; njp++)
            ldmx4(bb[njp], buf + boff0 + njp * 32);

        #pragma unroll
        for (int mi = 0; mi < 2; mi++)
            #pragma unroll
            for (int njp = 0; njp < 4; njp++) {
                mma_f16(acc[mi][njp * 2 + 0], a[mi], &bb[njp][0]);
                mma_f16(acc[mi][njp * 2 + 1], a[mi], &bb[njp][2]);
            }

        int nx = it + 3;
        if (nx < 8) {
            uint32_t dst = sb + (uint32_t)(nx & 3) * STAGE_B + soff;
            cp16(dst,       gptr + (size_t)nx * gstep);
            cp16(dst + 128, gptr + (size_t)nx * gstep + 64);
        }
        asm volatile("cp.async.commit_group;" ::: "memory");
    }

    __half* Mp = g_M16 + ((size_t)p * Kk + kb * 128 + wk) * NTP + (size_t)tb * 128 + wt;
    #pragma unroll
    for (int mi = 0; mi < 2; mi++) {
        #pragma unroll
        for (int nj = 0; nj < 8; nj++) {
            int t_off = nj * 8 + 2 * tig;
            __half* r0 = Mp + (size_t)(mi * 16 + g) * NTP + t_off;
            *(__half2*)r0                     = __floats2half2_rn(acc[mi][nj][0], acc[mi][nj][1]);
            *(__half2*)(r0 + (size_t)8 * NTP) = __floats2half2_rn(acc[mi][nj][2], acc[mi][nj][3]);
        }
    }
}

// ---------------------------------------------------------------------------
// 4) Inverse transform + bias, 2 tiles per thread (half2 M loads).
// ---------------------------------------------------------------------------
__global__ void __launch_bounds__(256) out_xform(const float* __restrict__ bias,
                                                 float* __restrict__ out)
{
    unsigned idx = blockIdx.x * blockDim.x + threadIdx.x;
    unsigned k  = idx / (NTP / 2u);
    unsigned tp = idx - k * (NTP / 2u);
    unsigned t  = 2u * tp;
    unsigned qq   = t & 31u;
    unsigned brow = t >> 5;
    unsigned b    = brow / 31u;
    unsigned pp   = brow - b * 31u;

    float mA[16], mB[16];
    #pragma unroll
    for (int p = 0; p < 16; p++) {
        __half2 h = *(const __half2*)&g_M16[((size_t)p * Kk + k) * NTP + t];
        float2 f = __half22float2(h);
        mA[p] = f.x; mB[p] = f.y;
    }

    float bv = __ldg(bias + k);

    float sA0[4], sA1[4], sB0[4], sB1[4];
    #pragma unroll
    for (int jj = 0; jj < 4; jj++) {
        sA0[jj] = mA[jj] + mA[4 + jj] + mA[8 + jj];
        sA1[jj] = mA[4 + jj] - mA[8 + jj] - mA[12 + jj];
        sB0[jj] = mB[jj] + mB[4 + jj] + mB[8 + jj];
        sB1[jj] = mB[4 + jj] - mB[8 + jj] - mB[12 + jj];
    }
    float yA00 = sA0[0] + sA0[1] + sA0[2] + bv;
    float yA01 = sA0[1] - sA0[2] - sA0[3] + bv;
    float yA10 = sA1[0] + sA1[1] + sA1[2] + bv;
    float yA11 = sA1[1] - sA1[2] - sA1[3] + bv;
    float yB00 = sB0[0] + sB0[1] + sB0[2] + bv;
    float yB01 = sB0[1] - sB0[2] - sB0[3] + bv;
    float yB10 = sB1[0] + sB1[1] + sB1[2] + bv;
    float yB11 = sB1[1] - sB1[2] - sB1[3] + bv;

    float* op = out + (((size_t)b * Kk + k) * OH + 2u * pp) * OW + 2u * qq;
    if (qq < 30u) {
        *(float4*)op = make_float4(yA00, yA01, yB00, yB01);
        *(float2*)(op + OW)     = make_float2(yA10, yA11);
        *(float2*)(op + OW + 2) = make_float2(yB10, yB11);
    } else {                       // qq == 30: second tile is pad
        *(float2*)op        = make_float2(yA00, yA01);
        *(float2*)(op + OW) = make_float2(yA10, yA11);
    }
}

// ---------------------------------------------------------------------------
extern "C" void kernel_launch(void* const* d_in, const int* in_sizes, int n_in,
                              void* d_out, int out_size)
{
    const float* x    = (const float*)d_in[0];
    const float* w    = (const float*)d_in[1];
    const float* bias = (const float*)d_in[2];
    float* out        = (float*)d_out;

    filt_xform<<<(Kk * Cc) / 256, 256>>>(w);
    in_xform<<<(Cc * NBR * 16) / 256, 256>>>(x);           // 7936 blocks
    dim3 g3(2, NTP / 128, 16);                             // (kb, tb, p)
    wino_gemm<<<g3, 256>>>();
    out_xform<<<(Kk * (NTP / 2)) / 256, 256>>>(bias, out); // 15872 blocks
}

// round 17
// speedup vs baseline: 1.1921x; 1.0061x over previous
#include <cuda_runtime.h>
#include <cuda_fp16.h>
#include <stdint.h>

// ---------------------------------------------------------------------------
// Winograd F(2,3) valid conv, fp16 mma.sync (m16n8k16, fp32 accum):
//   1) filt_xform : U[p][c][k] = G g G^T   (fp16; k-fastest lanes -> coalesced
//                   64B/warp plane stores; reads add only ~2MB of sectors)
//   2) in_xform   : V[p][c][t] = B^T d B   (fp16, 2 tiles/thread)
//   3) wino_gemm  : M[p][k][t] = sum_c U*V (fp16 HMMA, fp32 acc, fp16 M)
//   4) out_xform  : Y = A^T M A + bias     (2 tiles/thread, half2 loads)
// t = (b*31+pp)*32 + qq (qq padded to 32), NTP = 31744.  Pad t-columns are
// never consumed.  Identical to the measured-best (264.5us) config except
// the filt_xform thread->(k,c) mapping.
// ---------------------------------------------------------------------------

#define Bn 32
#define Cc 128
#define Hh 64
#define Ww 64
#define Kk 256
#define NBR 992               /* tile rows: 32 b * 31 pp */
#define NTP 31744             /* 992 * 32 = 248 * 128 */
#define OH 62
#define OW 62

__device__ __half g_U16[16 * Cc * Kk];    //   1 MB  [p][c][k]
__device__ __half g_V16[16 * Cc * NTP];   // 130 MB  [p][c][t]
__device__ __half g_M16[16 * Kk * NTP];   // 260 MB  [p][k][t]

__device__ __forceinline__ uint32_t smem_u32(const void* p) {
    uint32_t a;
    asm("{ .reg .u64 t; cvta.to.shared.u64 t, %1; cvt.u32.u64 %0, t; }" : "=r"(a) : "l"(p));
    return a;
}
__device__ __forceinline__ void cp16(uint32_t dst, const void* src) {
    asm volatile("cp.async.cg.shared.global [%0], [%1], 16;" :: "r"(dst), "l"(src));
}
__device__ __forceinline__ void ldmx4(uint32_t* r, uint32_t addr) {
    asm volatile("ldmatrix.sync.aligned.m8n8.x4.trans.shared.b16 {%0,%1,%2,%3}, [%4];"
                 : "=r"(r[0]), "=r"(r[1]), "=r"(r[2]), "=r"(r[3]) : "r"(addr));
}
__device__ __forceinline__ void mma_f16(float* d, const uint32_t* a, const uint32_t* b) {
    asm volatile(
        "mma.sync.aligned.m16n8k16.row.col.f32.f16.f16.f32 "
        "{%0,%1,%2,%3}, {%4,%5,%6,%7}, {%8,%9}, {%0,%1,%2,%3};"
        : "+f"(d[0]), "+f"(d[1]), "+f"(d[2]), "+f"(d[3])
        : "r"(a[0]), "r"(a[1]), "r"(a[2]), "r"(a[3]), "r"(b[0]), "r"(b[1]));
}

// ---------------------------------------------------------------------------
// 1) Filter transform -> U[p][c][k] fp16.  k fastest across lanes: each
//    plane store is 64 B contiguous per warp (vs 2 B x 512 B-stride scatter).
// ---------------------------------------------------------------------------
__global__ void filt_xform(const float* __restrict__ w)
{
    int idx = blockIdx.x * blockDim.x + threadIdx.x;   // 32768
    int k = idx & 255;          // k fastest across lanes
    int c = idx >> 8;
    const float* g = w + (size_t)(k * Cc + c) * 9;

    float w00 = g[0], w01 = g[1], w02 = g[2];
    float w10 = g[3], w11 = g[4], w12 = g[5];
    float w20 = g[6], w21 = g[7], w22 = g[8];

    float t[4][3];
    t[0][0] = w00;                      t[0][1] = w01;                      t[0][2] = w02;
    t[1][0] = 0.5f * (w00 + w10 + w20); t[1][1] = 0.5f * (w01 + w11 + w21); t[1][2] = 0.5f * (w02 + w12 + w22);
    t[2][0] = 0.5f * (w00 - w10 + w20); t[2][1] = 0.5f * (w01 - w11 + w21); t[2][2] = 0.5f * (w02 - w12 + w22);
    t[3][0] = w20;                      t[3][1] = w21;                      t[3][2] = w22;

    #pragma unroll
    for (int a = 0; a < 4; a++) {
        float u0 = t[a][0];
        float u1 = 0.5f * (t[a][0] + t[a][1] + t[a][2]);
        float u2 = 0.5f * (t[a][0] - t[a][1] + t[a][2]);
        float u3 = t[a][2];
        g_U16[((size_t)(a * 4 + 0) * Cc + c) * Kk + k] = __float2half_rn(u0);
        g_U16[((size_t)(a * 4 + 1) * Cc + c) * Kk + k] = __float2half_rn(u1);
        g_U16[((size_t)(a * 4 + 2) * Cc + c) * Kk + k] = __float2half_rn(u2);
        g_U16[((size_t)(a * 4 + 3) * Cc + c) * Kk + k] = __float2half_rn(u3);
    }
}

// ---------------------------------------------------------------------------
// 2) Input transform -> V[p][c][t], 2 horizontal tiles per thread.
//    Thread (c, brow, j): tiles qq = 2j, 2j+1 (j==15: only qq=30).
//    idx range = 128 * 992 * 16 = 2,031,616 = 7936 blocks * 256.
// ---------------------------------------------------------------------------
__global__ void __launch_bounds__(256) in_xform(const float* __restrict__ x)
{
    unsigned idx  = blockIdx.x * blockDim.x + threadIdx.x;
    unsigned j    = idx & 15u;
    unsigned rest = idx >> 4;           // c * 992 + brow
    unsigned c    = rest / NBR;
    unsigned brow = rest - c * NBR;
    unsigned b    = brow / 31u;
    unsigned pp   = brow - b * 31u;
    int qq0 = 2 * j;

    const float* xp = x + (((size_t)(b * Cc + c) * Hh + 2u * pp) * Ww + 2 * qq0);

    float d[4][6];
    if (j < 15) {
        #pragma unroll
        for (int i = 0; i < 4; i++) {
            float2 l0 = *(const float2*)(xp + i * Ww);
            float2 l1 = *(const float2*)(xp + i * Ww + 2);
            float2 l2 = *(const float2*)(xp + i * Ww + 4);
            d[i][0] = l0.x; d[i][1] = l0.y; d[i][2] = l1.x;
            d[i][3] = l1.y; d[i][4] = l2.x; d[i][5] = l2.y;
        }
    } else {
        #pragma unroll
        for (int i = 0; i < 4; i++) {
            float2 l0 = *(const float2*)(xp + i * Ww);
            float2 l1 = *(const float2*)(xp + i * Ww + 2);
            d[i][0] = l0.x; d[i][1] = l0.y; d[i][2] = l1.x;
            d[i][3] = l1.y; d[i][4] = 0.f;  d[i][5] = 0.f;
        }
    }

    float tm[4][6];
    #pragma unroll
    for (int jj = 0; jj < 6; jj++) {
        tm[0][jj] = d[0][jj] - d[2][jj];
        tm[1][jj] = d[1][jj] + d[2][jj];
        tm[2][jj] = d[2][jj] - d[1][jj];
        tm[3][jj] = d[1][jj] - d[3][jj];
    }

    size_t t0 = (size_t)brow * 32 + qq0;
    #pragma unroll
    for (int a = 0; a < 4; a++) {
        float vA0 = tm[a][0] - tm[a][2];
        float vA1 = tm[a][1] + tm[a][2];
        float vA2 = tm[a][2] - tm[a][1];
        float vA3 = tm[a][1] - tm[a][3];
        float vB0 = tm[a][2] - tm[a][4];
        float vB1 = tm[a][3] + tm[a][4];
        float vB2 = tm[a][4] - tm[a][3];
        float vB3 = tm[a][3] - tm[a][5];
        *(__half2*)&g_V16[((size_t)(a * 4 + 0) * Cc + c) * NTP + t0] = __floats2half2_rn(vA0, vB0);
        *(__half2*)&g_V16[((size_t)(a * 4 + 1) * Cc + c) * NTP + t0] = __floats2half2_rn(vA1, vB1);
        *(__half2*)&g_V16[((size_t)(a * 4 + 2) * Cc + c) * NTP + t0] = __floats2half2_rn(vA2, vB2);
        *(__half2*)&g_V16[((size_t)(a * 4 + 3) * Cc + c) * NTP + t0] = __floats2half2_rn(vA3, vB3);
    }
}

// ---------------------------------------------------------------------------
// 3) fp16 tensor GEMM:  M[k][t] = sum_c U[c][k]*V[c][t], per point p.
//    CTA 128k x 128t, 256 thr, warp 32k x 64t, 16-c chunks, 8 iterations,
//    4-stage cp.async ring, 1 sync/chunk, ldmatrix.x4.trans.
//    grid = (kb=2 fastest, tb=248, p=16)
// ---------------------------------------------------------------------------
#define PITCH_B 272             /* bytes per smem row (136 halves) */
#define UREG_B  4352            /* 16 rows * 272 */
#define STAGE_B 8704            /* U + V regions */

__global__ void __launch_bounds__(256, 2) wino_gemm()
{
    __shared__ alignas(16) char smem[4 * STAGE_B];
    const uint32_t sb = smem_u32(smem);

    const int kb = blockIdx.x;          // 0..1
    const int tb = blockIdx.y;          // 0..247
    const int p  = blockIdx.z;          // 0..15

    const int tid  = threadIdx.x;
    const int wid  = tid >> 5, lane = tid & 31;
    const int g    = lane >> 2, tig = lane & 3;
    const int wk   = (wid & 3) * 32;
    const int wt   = (wid >> 2) * 64;

    const __half* gptr;
    size_t gstep;
    uint32_t soff;
    {
        if (tid < 128) {                 // U: 16 c-rows x 128 k halves
            int row = tid >> 3, seg = tid & 7;
            gptr  = g_U16 + ((size_t)p * Cc + row) * Kk + kb * 128 + seg * 8;
            gstep = (size_t)16 * Kk;
            soff  = (uint32_t)(row * PITCH_B + seg * 16);
        } else {                         // V: 16 c-rows x 128 t halves
            int jj = tid - 128;
            int row = jj >> 3, seg = jj & 7;
            gptr  = g_V16 + ((size_t)p * Cc + row) * NTP + (size_t)tb * 128 + seg * 8;
            gstep = (size_t)16 * NTP;
            soff  = (uint32_t)(UREG_B + row * PITCH_B + seg * 16);
        }
    }

    const uint32_t aoff0 = (uint32_t)(((lane & 7) + ((lane >> 4) & 1) * 8) * PITCH_B
                                      + (wk + ((lane >> 3) & 1) * 8) * 2);
    const uint32_t boff0 = (uint32_t)(UREG_B
                                      + ((lane & 7) + ((lane >> 3) & 1) * 8) * PITCH_B
                                      + (wt + ((lane >> 4) & 1) * 8) * 2);

    float acc[2][8][4];
    #pragma unroll
    for (int mi = 0; mi < 2; mi++)
        #pragma unroll
        for (int nj = 0; nj < 8; nj++)
            #pragma unroll
            for (int q = 0; q < 4; q++)
                acc[mi][nj][q] = 0.0f;

    #pragma unroll
    for (int s = 0; s < 3; s++) {
        uint32_t dst = sb + (uint32_t)s * STAGE_B + soff;
        cp16(dst,       gptr + (size_t)s * gstep);
        cp16(dst + 128, gptr + (size_t)s * gstep + 64);
        asm volatile("cp.async.commit_group;" ::: "memory");
    }

    #pragma unroll 1
    for (int it = 0; it < 8; it++) {
        asm volatile("cp.async.wait_group %0;" :: "n"(2) : "memory");
        __syncthreads();

        const uint32_t buf = sb + (uint32_t)(it & 3) * STAGE_B;

        uint32_t a[2][4];
        ldmx4(a[0], buf + aoff0);
        ldmx4(a[1], buf + aoff0 + 32);
        uint32_t bb[4][4];
        #pragma unroll
        for (int njp = 0; njp < 4; njp++)
            ldmx4(bb[njp], buf + boff0 + njp * 32);

        #pragma unroll
        for (int mi = 0; mi < 2; mi++)
            #pragma unroll
            for (int njp = 0; njp < 4; njp++) {
                mma_f16(acc[mi][njp * 2 + 0], a[mi], &bb[njp][0]);
                mma_f16(acc[mi][njp * 2 + 1], a[mi], &bb[njp][2]);
            }

        int nx = it + 3;
        if (nx < 8) {
            uint32_t dst = sb + (uint32_t)(nx & 3) * STAGE_B + soff;
            cp16(dst,       gptr + (size_t)nx * gstep);
            cp16(dst + 128, gptr + (size_t)nx * gstep + 64);
        }
        asm volatile("cp.async.commit_group;" ::: "memory");
    }

    __half* Mp = g_M16 + ((size_t)p * Kk + kb * 128 + wk) * NTP + (size_t)tb * 128 + wt;
    #pragma unroll
    for (int mi = 0; mi < 2; mi++) {
        #pragma unroll
        for (int nj = 0; nj < 8; nj++) {
            int t_off = nj * 8 + 2 * tig;
            __half* r0 = Mp + (size_t)(mi * 16 + g) * NTP + t_off;
            *(__half2*)r0                     = __floats2half2_rn(acc[mi][nj][0], acc[mi][nj][1]);
            *(__half2*)(r0 + (size_t)8 * NTP) = __floats2half2_rn(acc[mi][nj][2], acc[mi][nj][3]);
        }
    }
}

// ---------------------------------------------------------------------------
// 4) Inverse transform + bias, 2 tiles per thread (half2 M loads).
// ---------------------------------------------------------------------------
__global__ void __launch_bounds__(256) out_xform(const float* __restrict__ bias,
                                                 float* __restrict__ out)
{
    unsigned idx = blockIdx.x * blockDim.x + threadIdx.x;
    unsigned k  = idx / (NTP / 2u);
    unsigned tp = idx - k * (NTP / 2u);
    unsigned t  = 2u * tp;
    unsigned qq   = t & 31u;
    unsigned brow = t >> 5;
    unsigned b    = brow / 31u;
    unsigned pp   = brow - b * 31u;

    float mA[16], mB[16];
    #pragma unroll
    for (int p = 0; p < 16; p++) {
        __half2 h = *(const __half2*)&g_M16[((size_t)p * Kk + k) * NTP + t];
        float2 f = __half22float2(h);
        mA[p] = f.x; mB[p] = f.y;
    }

    float bv = __ldg(bias + k);

    float sA0[4], sA1[4], sB0[4], sB1[4];
    #pragma unroll
    for (int jj = 0; jj < 4; jj++) {
        sA0[jj] = mA[jj] + mA[4 + jj] + mA[8 + jj];
        sA1[jj] = mA[4 + jj] - mA[8 + jj] - mA[12 + jj];
        sB0[jj] = mB[jj] + mB[4 + jj] + mB[8 + jj];
        sB1[jj] = mB[4 + jj] - mB[8 + jj] - mB[12 + jj];
    }
    float yA00 = sA0[0] + sA0[1] + sA0[2] + bv;
    float yA01 = sA0[1] - sA0[2] - sA0[3] + bv;
    float yA10 = sA1[0] + sA1[1] + sA1[2] + bv;
    float yA11 = sA1[1] - sA1[2] - sA1[3] + bv;
    float yB00 = sB0[0] + sB0[1] + sB0[2] + bv;
    float yB01 = sB0[1] - sB0[2] - sB0[3] + bv;
    float yB10 = sB1[0] + sB1[1] + sB1[2] + bv;
    float yB11 = sB1[1] - sB1[2] - sB1[3] + bv;

    float* op = out + (((size_t)b * Kk + k) * OH + 2u * pp) * OW + 2u * qq;
    if (qq < 30u) {
        *(float4*)op = make_float4(yA00, yA01, yB00, yB01);
        *(float2*)(op + OW)     = make_float2(yA10, yA11);
        *(float2*)(op + OW + 2) = make_float2(yB10, yB11);
    } else {                       // qq == 30: second tile is pad
        *(float2*)op        = make_float2(yA00, yA01);
        *(float2*)(op + OW) = make_float2(yA10, yA11);
    }
}

// ---------------------------------------------------------------------------
extern "C" void kernel_launch(void* const* d_in, const int* in_sizes, int n_in,
                              void* d_out, int out_size)
{
    const float* x    = (const float*)d_in[0];
    const float* w    = (const float*)d_in[1];
    const float* bias = (const float*)d_in[2];
    float* out        = (float*)d_out;

    filt_xform<<<(Kk * Cc) / 256, 256>>>(w);
    in_xform<<<(Cc * NBR * 16) / 256, 256>>>(x);           // 7936 blocks
    dim3 g3(2, NTP / 128, 16);                             // (kb, tb, p)
    wino_gemm<<<g3, 256>>>();
    out_xform<<<(Kk * (NTP / 2)) / 256, 256>>>(bias, out); // 15872 blocks
}